// round 16
// baseline (speedup 1.0000x reference)
#include <cuda_runtime.h>
#include <cuda_bf16.h>
#include <math.h>

typedef unsigned long long ull;

// ---------------- problem constants ----------------
#define BB   64
#define SS   256
#define LL   16
#define CE   50
#define EE   100
#define HH   300
#define IN0  150
#define IN1  600
#define NCLS 50
#define BS   (BB*SS)     // 16384
#define CG   (4*CE)      // 200
#define HG   (4*HH)      // 1200
#define CVOC 128

// padded strides
#define CEP  56
#define IN0P 152
#define NP_C 256
#define NP_B 2432
#define XST  204         // char x smem row stride (16B aligned)

// pack buffer offsets (floats)
#define PK_C0 0
#define PK_C1 (CEP*NP_C)
#define PK_B0 (2*CEP*NP_C)
#define PK_B1 (PK_B0 + IN0P*NP_B)
#define PK_TOT (PK_B1 + IN1*NP_B)

// ---------------- device scratch ----------------
__device__ float g_ctab[CVOC*CG];            // layer-0 x-gate table [128][200]
__device__ float g_cxg [(long)LL*BS*CG];     // layer-1 xg
__device__ float g_chs [(long)LL*BS*CEP];    // layer-0 h sequence (layer-1 GEMM input)
__device__ float g_seqin[SS*BB*IN0P];
__device__ float g_bxg [(long)SS*BB*2*HG];
__device__ float g_h0  [(long)SS*BB*2*HH];
__device__ float g_h1  [(long)SS*BB*2*HH];
__device__ float g_bh  [2*2*BB*HH];
__device__ float g_bpack[PK_TOT];

// barrier state
__device__ unsigned g_flags[2][1920];
__device__ volatile unsigned g_gen2[2];

// ---------------- helpers ----------------
__device__ __forceinline__ float sigf(float x) { return 1.f / (1.f + expf(-x)); }

__device__ __forceinline__ ull pk2(float x, float y) {
    ull r; asm("mov.b64 %0, {%1,%2};" : "=l"(r) : "f"(x), "f"(y)); return r;
}
__device__ __forceinline__ ull f2fma(ull a, ull b, ull c) {
    ull d; asm("fma.rn.f32x2 %0, %1, %2, %3;" : "=l"(d) : "l"(a), "l"(b), "l"(c)); return d;
}
__device__ __forceinline__ void unpk2(ull v, float& x, float& y) {
    asm("mov.b64 {%0,%1}, %2;" : "=f"(x), "=f"(y) : "l"(v));
}
__device__ __forceinline__ float sum2(ull v) { float x, y; unpk2(v, x, y); return x + y; }

// ---------------- two-level flag barrier (R12, measured-good) ----------------
__device__ __forceinline__ void gsync2(int dir, int lbk, unsigned &lg) {
    __syncthreads();
    const unsigned target = lg + 1;
    if (threadIdx.x == 0) {
        __threadfence();
        *(volatile unsigned*)&g_flags[dir][lbk * 32] = target;
    }
    if (lbk == 0) {
        if (threadIdx.x < 60) {
            volatile unsigned* f = &g_flags[dir][threadIdx.x * 32];
            int spins = 0;
            while (*f < target) { if (++spins > 512) __nanosleep(32); }
        }
        __syncthreads();
        if (threadIdx.x == 0) {
            __threadfence();
            g_gen2[dir] = target;
        }
    } else {
        if (threadIdx.x == 0) {
            int spins = 0;
            while (g_gen2[dir] < target) { if (++spins > 512) __nanosleep(32); }
            __threadfence();
        }
    }
    __syncthreads();
    lg = target;
}

// ---------------- ctable: flags reset + char layer-0 vocab table + seqin word part ----------------
__global__ void k_ctable(const float* __restrict__ char_embed, const float* __restrict__ cWih,
                         const float* __restrict__ cbih, const float* __restrict__ cbhh,
                         const int* __restrict__ word_ids, const float* __restrict__ word_embed,
                         float* __restrict__ table, float* __restrict__ seqin) {
    if (blockIdx.x == 0) {
        for (int e = threadIdx.x; e < 2 * 1920; e += 256)
            ((unsigned*)g_flags)[e] = 0;
        if (threadIdx.x < 2) g_gen2[threadIdx.x] = 0;
    }
    const long NT = (long)CVOC * CG;           // 25600
    const long NS = (long)SS * BB * IN0P;
    long i = (long)blockIdx.x * blockDim.x + threadIdx.x;
    if (i < NT) {
        int v = (int)(i / CG), g = (int)(i % CG);
        float acc = cbih[g] + cbhh[g];
        const float* ev = char_embed + (long)v * CE;
        const float* wv = cWih + (long)g * CE;
#pragma unroll 10
        for (int k = 0; k < CE; k++) acc += ev[k] * wv[k];
        table[i] = acc;
    } else if (i < NT + NS) {
        long i2 = i - NT;
        int d = (int)(i2 % IN0P);
        long r = i2 / IN0P;
        int b = (int)(r & 63);
        int s = (int)(r >> 6);
        if (d < EE)
            seqin[i2] = word_embed[(long)word_ids[(long)b * SS + s] * EE + d];
        else if (d >= IN0)
            seqin[i2] = 0.f;
        // d in [100,150): written by char layer-1 persist
    }
}

// ---------------- pack all weights ----------------
__global__ void k_packall(const float* __restrict__ cWih,
                          const float* __restrict__ b0Wih,
                          const float* __restrict__ b1Wih,
                          float* __restrict__ dst) {
    for (long i = (long)blockIdx.x * blockDim.x + threadIdx.x; i < PK_TOT;
         i += (long)gridDim.x * blockDim.x) {
        float v = 0.f;
        if (i < PK_B0) {
            int lay = (i >= PK_C1);
            long i2 = i - (lay ? PK_C1 : 0);
            int k = (int)(i2 / NP_C), n = (int)(i2 % NP_C);
            if (n < CG && k < CE) v = cWih[(long)lay * CG * CE + (long)n * CE + k];
        } else if (i < PK_B1) {
            long i2 = i - PK_B0;
            int k = (int)(i2 / NP_B), n = (int)(i2 % NP_B);
            if (n < 2 * HG && k < IN0) v = b0Wih[(long)n * IN0 + k];
        } else {
            long i2 = i - PK_B1;
            int k = (int)(i2 / NP_B), n = (int)(i2 % NP_B);
            if (n < 2 * HG && k < IN1) v = b1Wih[(long)n * IN1 + k];
        }
        dst[i] = v;
    }
}

// ---------------- GEMM v3: duplicated-A smem (broadcast-safe), no pack movs ----------------
__global__ __launch_bounds__(256, 2) void k_gemm(
    const float* __restrict__ A, int lda,
    const float* __restrict__ Bp, int NP,
    const float* __restrict__ bias1, const float* __restrict__ bias2,
    float* __restrict__ C, int N, int ldc, int kt)
{
    __shared__ __align__(16) float Ad[2][8][256];   // Ad[k][2r]=Ad[k][2r+1]=A[r]
    __shared__ __align__(16) float Bs[2][8][128];
    const int tid = threadIdx.x;
    const int tx = tid & 15, ty = tid >> 4;
    const int row0 = blockIdx.y * 128, col0 = blockIdx.x * 128;

    ull acc[8][4];
#pragma unroll
    for (int i = 0; i < 8; i++)
#pragma unroll
        for (int jp = 0; jp < 4; jp++) acc[i][jp] = 0ull;

    const int ar = tid >> 1, ak = (tid & 1) * 4;
    const int bk = tid >> 5, bn = (tid & 31) * 4;
    const float* Aptr = A + (long)(row0 + ar) * lda + ak;
    const float* Bptr = Bp + (long)bk * NP + col0 + bn;

    {
        float4 av = *(const float4*)Aptr;
        *(ull*)&Ad[0][ak + 0][2 * ar] = pk2(av.x, av.x);
        *(ull*)&Ad[0][ak + 1][2 * ar] = pk2(av.y, av.y);
        *(ull*)&Ad[0][ak + 2][2 * ar] = pk2(av.z, av.z);
        *(ull*)&Ad[0][ak + 3][2 * ar] = pk2(av.w, av.w);
        *(float4*)&Bs[0][bk][bn] = *(const float4*)Bptr;
    }
    __syncthreads();

    for (int it = 0; it < kt; it++) {
        int cur = it & 1;
        if (it + 1 < kt) {
            float4 av = *(const float4*)(Aptr + (it + 1) * 8);
            float4 bv = *(const float4*)(Bptr + (long)(it + 1) * 8 * NP);
            *(ull*)&Ad[cur ^ 1][ak + 0][2 * ar] = pk2(av.x, av.x);
            *(ull*)&Ad[cur ^ 1][ak + 1][2 * ar] = pk2(av.y, av.y);
            *(ull*)&Ad[cur ^ 1][ak + 2][2 * ar] = pk2(av.z, av.z);
            *(ull*)&Ad[cur ^ 1][ak + 3][2 * ar] = pk2(av.w, av.w);
            *(float4*)&Bs[cur ^ 1][bk][bn] = bv;
        }
#pragma unroll
        for (int k = 0; k < 8; k++) {
            // A: broadcast reads (2 distinct addrs/warp), conflict-free
            ulonglong2 aA = *(const ulonglong2*)&Ad[cur][k][ty * 8];          // rows ty*4+0,1
            ulonglong2 aB = *(const ulonglong2*)&Ad[cur][k][ty * 8 + 4];      // rows ty*4+2,3
            ulonglong2 aC = *(const ulonglong2*)&Ad[cur][k][128 + ty * 8];    // rows 64+ty*4+0,1
            ulonglong2 aD = *(const ulonglong2*)&Ad[cur][k][128 + ty * 8 + 4];
            ulonglong2 b0 = *(const ulonglong2*)&Bs[cur][k][tx * 4];
            ulonglong2 b1 = *(const ulonglong2*)&Bs[cur][k][64 + tx * 4];
            ull ap[8] = { aA.x, aA.y, aB.x, aB.y, aC.x, aC.y, aD.x, aD.y };
#pragma unroll
            for (int i = 0; i < 8; i++) {
                acc[i][0] = f2fma(ap[i], b0.x, acc[i][0]);
                acc[i][1] = f2fma(ap[i], b0.y, acc[i][1]);
                acc[i][2] = f2fma(ap[i], b1.x, acc[i][2]);
                acc[i][3] = f2fma(ap[i], b1.y, acc[i][3]);
            }
        }
        __syncthreads();
    }

#pragma unroll
    for (int i = 0; i < 8; i++) {
        int r = row0 + (i < 4 ? ty * 4 + i : 64 + ty * 4 + (i - 4));
#pragma unroll
        for (int jp = 0; jp < 4; jp++) {
            float x, y; unpk2(acc[i][jp], x, y);
            int c0 = col0 + (jp < 2 ? tx * 4 + jp * 2 : 64 + tx * 4 + (jp - 2) * 2);
            if (c0 < N)     C[(long)r * ldc + c0]     = x + bias1[c0] + bias2[c0];
            if (c0 + 1 < N) C[(long)r * ldc + c0 + 1] = y + bias1[c0 + 1] + bias2[c0 + 1];
        }
    }
}

// ---------------- char LSTM layer: h in smem; x from cxg (L1) or vocab table (L0) ----------------
#define CHP_SMEM (((200*52 + 64*XST + 64*52) * 4) + 4096)
__global__ __launch_bounds__(256, 2) void k_char_persist(
    const float* __restrict__ Whh,      // [200][50]
    const float* __restrict__ xg,       // [16][BS][200] or NULL (L0)
    const float* __restrict__ xtable,   // [128][200] or NULL (L1)
    const int*   __restrict__ char_ids, // [BS][16] (L0 only)
    float* __restrict__ hseq,           // [16][BS][56] or NULL
    float* __restrict__ seqchar)        // seqin base or NULL (L1: write char slice at t=15)
{
    extern __shared__ float sm[];
    float* Ws  = sm;                        // [200][52]
    float* xs  = sm + 200 * 52;             // [64][XST]
    float* hsm = sm + 200 * 52 + 64 * XST;  // [64][52]
    int*   ids = (int*)(sm + 200 * 52 + 64 * XST + 64 * 52);  // [64*16]
    const int tid = threadIdx.x;
    const int nl  = tid & 63;
    const int jg  = tid >> 6;        // 0..3
    const int n0  = blockIdx.x * 64;
    const int jb  = jg * 13;

    for (int e = tid; e < 200 * 52; e += 256) {
        int k = e % 52, r = e / 52;
        Ws[e] = (k < 50) ? Whh[r * 50 + k] : 0.f;
    }
    for (int e = tid; e < 64 * 52; e += 256) hsm[e] = 0.f;
    if (xtable) {
        for (int e = tid; e < 64 * LL; e += 256) ids[e] = char_ids[(long)n0 * LL + e];
    }
    float c[13];
#pragma unroll
    for (int q = 0; q < 13; q++) c[q] = 0.f;
    __syncthreads();

    for (int t = 0; t < LL; t++) {
        if (xtable) {
            for (int e = tid; e < 64 * 50; e += 256) {
                int n = e / 50, q = e % 50;
                int id = ids[n * LL + t];
                *(float4*)&xs[n * XST + q * 4] = *(const float4*)&xtable[(long)id * CG + q * 4];
            }
        } else {
            const float4* xsrc = (const float4*)(xg + ((long)t * BS + n0) * CG);
            for (int e = tid; e < 64 * 50; e += 256) {
                int n = e / 50, q = e % 50;
                *(float4*)&xs[n * XST + q * 4] = xsrc[(long)n * 50 + q];
            }
        }
        __syncthreads();

        ulonglong2 hreg[13];
        {
            const ulonglong2* hp = (const ulonglong2*)(hsm + nl * 52);
#pragma unroll
            for (int q = 0; q < 13; q++) hreg[q] = hp[q];
        }
        __syncthreads();

        const float* xrow = xs + nl * XST;
#pragma unroll
        for (int jj = 0; jj < 13; jj++) {
            int jv = jb + jj;
            bool act = (jv < 50);
            int jvc = act ? jv : 0;
            ull a0 = 0ull, a1 = 0ull, a2 = 0ull, a3 = 0ull;
            const ulonglong2* wi = (const ulonglong2*)(Ws + (      jvc) * 52);
            const ulonglong2* wf = (const ulonglong2*)(Ws + ( 50 + jvc) * 52);
            const ulonglong2* wg = (const ulonglong2*)(Ws + (100 + jvc) * 52);
            const ulonglong2* wo = (const ulonglong2*)(Ws + (150 + jvc) * 52);
#pragma unroll
            for (int q = 0; q < 13; q++) {
                ulonglong2 hv = hreg[q];
                ulonglong2 w;
                w = wi[q]; a0 = f2fma(w.x, hv.x, a0); a0 = f2fma(w.y, hv.y, a0);
                w = wf[q]; a1 = f2fma(w.x, hv.x, a1); a1 = f2fma(w.y, hv.y, a1);
                w = wg[q]; a2 = f2fma(w.x, hv.x, a2); a2 = f2fma(w.y, hv.y, a2);
                w = wo[q]; a3 = f2fma(w.x, hv.x, a3); a3 = f2fma(w.y, hv.y, a3);
            }
            if (act) {
                float g0 = sum2(a0) + xrow[jv];
                float g1 = sum2(a1) + xrow[50 + jv];
                float g2 = sum2(a2) + xrow[100 + jv];
                float g3 = sum2(a3) + xrow[150 + jv];
                float cn = sigf(g1) * c[jj] + sigf(g0) * tanhf(g2);
                float h  = sigf(g3) * tanhf(cn);
                c[jj] = cn;
                hsm[nl * 52 + jv] = h;
            }
        }
        __syncthreads();
        if (hseq) {
            float* sd = hseq + ((long)t * BS + n0) * CEP;
            for (int e = tid; e < 64 * CEP; e += 256) {
                int n = e / CEP, k = e % CEP;
                sd[e] = (k < 50) ? hsm[n * 52 + k] : 0.f;
            }
        }
        if (seqchar && t == LL - 1) {
            int b  = n0 / SS;
            int s0 = n0 % SS;
            for (int e = tid; e < 64 * 50; e += 256) {
                int nlw = e / 50, k = e % 50;
                seqchar[((long)(s0 + nlw) * BB + b) * IN0P + EE + k] = hsm[nlw * 52 + k];
            }
        }
    }
}

// ---------------- persistent bilstm layer (R12-exact: 160 thr, 2 batches/thread) ----------------
#define BLP_NBLK 120
#define BLP_NT   160
#define BLP_SMEM ((6000 + 64*308) * 4)
__global__ __launch_bounds__(BLP_NT, 1) void k_bilstm_persist(
    const float* __restrict__ Whh,   // [2][1200][300]
    const float* __restrict__ xg,    // [256][64][2400]
    float* __restrict__ hbuf,        // [2 ping][2 dir][64][300]
    float* __restrict__ seq,         // [256][64][600]
    unsigned gbase)
{
    extern __shared__ float sm[];
    float* Ws = sm;           // [4 gate][5 unit][300]
    float* hs = sm + 6000;    // [64][308]
    const int bk  = blockIdx.x;
    const int dir = bk / 60;
    const int lbk = bk % 60;
    const int jbase = lbk * 5;
    const int tid = threadIdx.x;
    const int ul = tid % 5;
    const int b2 = tid / 5;          // 0..31
    const int ba = 2 * b2, bbn = 2 * b2 + 1;
    const int j  = jbase + ul;
    unsigned lg = gbase;

    const float* wb = Whh + (long)dir * HG * HH;
    for (int e = tid; e < 6000; e += BLP_NT) {
        int k = e % 300; int r = e / 300; int u = r % 5; int g = r / 5;
        Ws[e] = wb[(long)(g * 300 + jbase + u) * 300 + k];
    }
    for (int e = lbk * BLP_NT + tid; e < BB * HH; e += 60 * BLP_NT)
        hbuf[(long)dir * BB * HH + e] = 0.f;
    float ca = 0.f, cb = 0.f;

    float xr[8];
    {
        int te = dir ? (SS - 1) : 0;
        const float* xa = xg + ((long)te * BB + ba)  * (2 * HG) + dir * HG;
        const float* xv = xg + ((long)te * BB + bbn) * (2 * HG) + dir * HG;
        xr[0] = xa[j]; xr[1] = xa[300 + j]; xr[2] = xa[600 + j]; xr[3] = xa[900 + j];
        xr[4] = xv[j]; xr[5] = xv[300 + j]; xr[6] = xv[600 + j]; xr[7] = xv[900 + j];
    }
    gsync2(dir, lbk, lg);

    const ulonglong2* w0 = (const ulonglong2*)(Ws + (0 * 5 + ul) * 300);
    const ulonglong2* w1 = (const ulonglong2*)(Ws + (1 * 5 + ul) * 300);
    const ulonglong2* w2 = (const ulonglong2*)(Ws + (2 * 5 + ul) * 300);
    const ulonglong2* w3 = (const ulonglong2*)(Ws + (3 * 5 + ul) * 300);
    float4* hs4 = (float4*)hs;

    for (int t = 0; t < SS; t++) {
        int pp = t & 1;
        int te = dir ? (SS - 1 - t) : t;

        const float4* src = (const float4*)(hbuf + ((long)pp * 2 + dir) * BB * HH);
        for (int e = tid; e < 4800; e += BLP_NT) {
            int bb = e / 75, k4 = e % 75;
            hs4[bb * 77 + k4] = src[e];
        }
        __syncthreads();

        ull a0 = 0ull, a1 = 0ull, a2 = 0ull, a3 = 0ull;
        ull d0 = 0ull, d1 = 0ull, d2 = 0ull, d3 = 0ull;
        const ulonglong2* ra = (const ulonglong2*)(hs + ba  * 308);
        const ulonglong2* rb = (const ulonglong2*)(hs + bbn * 308);
#pragma unroll
        for (int q = 0; q < 75; q++) {
            ulonglong2 ha = ra[q];
            ulonglong2 hb = rb[q];
            ulonglong2 w;
            w = w0[q]; a0 = f2fma(w.x, ha.x, a0); a0 = f2fma(w.y, ha.y, a0);
                       d0 = f2fma(w.x, hb.x, d0); d0 = f2fma(w.y, hb.y, d0);
            w = w1[q]; a1 = f2fma(w.x, ha.x, a1); a1 = f2fma(w.y, ha.y, a1);
                       d1 = f2fma(w.x, hb.x, d1); d1 = f2fma(w.y, hb.y, d1);
            w = w2[q]; a2 = f2fma(w.x, ha.x, a2); a2 = f2fma(w.y, ha.y, a2);
                       d2 = f2fma(w.x, hb.x, d2); d2 = f2fma(w.y, hb.y, d2);
            w = w3[q]; a3 = f2fma(w.x, ha.x, a3); a3 = f2fma(w.y, ha.y, a3);
                       d3 = f2fma(w.x, hb.x, d3); d3 = f2fma(w.y, hb.y, d3);
        }
        {
            float g0 = sum2(a0) + xr[0];
            float g1 = sum2(a1) + xr[1];
            float g2 = sum2(a2) + xr[2];
            float g3 = sum2(a3) + xr[3];
            float cn = sigf(g1) * ca + sigf(g0) * tanhf(g2);
            float h  = sigf(g3) * tanhf(cn);
            ca = cn;
            hbuf[((long)(pp ^ 1) * 2 + dir) * BB * HH + ba * HH + j] = h;
            seq[((long)te * BB + ba) * (2 * HH) + dir * HH + j] = h;
        }
        {
            float g0 = sum2(d0) + xr[4];
            float g1 = sum2(d1) + xr[5];
            float g2 = sum2(d2) + xr[6];
            float g3 = sum2(d3) + xr[7];
            float cn = sigf(g1) * cb + sigf(g0) * tanhf(g2);
            float h  = sigf(g3) * tanhf(cn);
            cb = cn;
            hbuf[((long)(pp ^ 1) * 2 + dir) * BB * HH + bbn * HH + j] = h;
            seq[((long)te * BB + bbn) * (2 * HH) + dir * HH + j] = h;
        }
        if (t + 1 < SS) {
            int te2 = dir ? (SS - 2 - t) : (t + 1);
            const float* xa = xg + ((long)te2 * BB + ba)  * (2 * HG) + dir * HG;
            const float* xv = xg + ((long)te2 * BB + bbn) * (2 * HG) + dir * HG;
            xr[0] = xa[j]; xr[1] = xa[300 + j]; xr[2] = xa[600 + j]; xr[3] = xa[900 + j];
            xr[4] = xv[j]; xr[5] = xv[300 + j]; xr[6] = xv[600 + j]; xr[7] = xv[900 + j];
        }
        gsync2(dir, lbk, lg);
    }
}

// ---------------- FC + log-softmax: 8 rows per block, 512 threads ----------------
__global__ __launch_bounds__(512) void k_fc_lsm(
    const float* __restrict__ h1, const float* __restrict__ fcW,
    const float* __restrict__ fcb, float* __restrict__ out) {
    __shared__ float hrow[8 * IN1];
    __shared__ float logits[8 * NCLS];
    __shared__ float lse[8];
    const int tid = threadIdx.x;
    const int r0 = blockIdx.x * 8;
    for (int e = tid; e < 8 * IN1; e += 512) hrow[e] = h1[(long)r0 * IN1 + e];
    __syncthreads();
    const int rl = tid / NCLS, cc = tid % NCLS;
    if (tid < 8 * NCLS) {
        float acc = 0.f;
        const float4* w  = (const float4*)(fcW + cc * IN1);
        const float4* hv = (const float4*)(hrow + rl * IN1);
#pragma unroll 10
        for (int k = 0; k < IN1 / 4; k++) {
            float4 a = __ldg(w + k), x = hv[k];
            acc += a.x * x.x + a.y * x.y + a.z * x.z + a.w * x.w;
        }
        logits[rl * NCLS + cc] = acc + fcb[cc];
    }
    __syncthreads();
    if (tid < 8) {
        float m = -1e30f;
        for (int c = 0; c < NCLS; c++) m = fmaxf(m, logits[tid * NCLS + c]);
        float sum = 0.f;
        for (int c = 0; c < NCLS; c++) sum += expf(logits[tid * NCLS + c] - m);
        lse[tid] = m + logf(sum);
    }
    __syncthreads();
    if (tid < 8 * NCLS) {
        int r = r0 + rl;
        int s = r >> 6, b = r & 63;
        out[((long)(b * SS + s)) * NCLS + cc] = logits[rl * NCLS + cc] - lse[rl];
    }
}

// ---------------- host orchestration ----------------
extern "C" void kernel_launch(void* const* d_in, const int* in_sizes, int n_in,
                              void* d_out, int out_size) {
    const int*   word_ids   = (const int*)  d_in[0];
    const int*   char_ids   = (const int*)  d_in[1];
    const float* word_embed = (const float*)d_in[2];
    const float* char_embed = (const float*)d_in[3];
    const float* cWih  = (const float*)d_in[4];
    const float* cWhh  = (const float*)d_in[5];
    const float* cbih  = (const float*)d_in[6];
    const float* cbhh  = (const float*)d_in[7];
    const float* b0Wih = (const float*)d_in[8];
    const float* b0Whh = (const float*)d_in[9];
    const float* b0bih = (const float*)d_in[10];
    const float* b0bhh = (const float*)d_in[11];
    const float* b1Wih = (const float*)d_in[12];
    const float* b1Whh = (const float*)d_in[13];
    const float* b1bih = (const float*)d_in[14];
    const float* b1bhh = (const float*)d_in[15];
    const float* fcW   = (const float*)d_in[16];
    const float* fcb   = (const float*)d_in[17];
    float* out = (float*)d_out;

    float *ctab, *cxg, *chs, *seqin, *bxg, *h0, *h1, *bh, *bpack;
    cudaGetSymbolAddress((void**)&ctab,  g_ctab);
    cudaGetSymbolAddress((void**)&cxg,   g_cxg);
    cudaGetSymbolAddress((void**)&chs,   g_chs);
    cudaGetSymbolAddress((void**)&seqin, g_seqin);
    cudaGetSymbolAddress((void**)&bxg,   g_bxg);
    cudaGetSymbolAddress((void**)&h0,    g_h0);
    cudaGetSymbolAddress((void**)&h1,    g_h1);
    cudaGetSymbolAddress((void**)&bh,    g_bh);
    cudaGetSymbolAddress((void**)&bpack, g_bpack);

    cudaFuncSetAttribute(k_char_persist,   cudaFuncAttributeMaxDynamicSharedMemorySize, CHP_SMEM);
    cudaFuncSetAttribute(k_bilstm_persist, cudaFuncAttributeMaxDynamicSharedMemorySize, BLP_SMEM);

    // 1: ctable (flags reset + vocab table + seqin word part)
    {
        long n = (long)CVOC * CG + (long)SS * BB * IN0P;
        k_ctable<<<(int)((n + 255) / 256), 256>>>(char_embed, cWih, cbih, cbhh,
                                                  word_ids, word_embed, ctab, seqin);
    }
    // 2: pack all weights
    k_packall<<<2048, 256>>>(cWih, b0Wih, b1Wih, bpack);
    // 3: char layer 0 (x from vocab table; writes chs)
    k_char_persist<<<256, 256, CHP_SMEM>>>(cWhh, nullptr, ctab, char_ids, chs, nullptr);
    // 4: char layer-1 input gemm
    {
        dim3 grid(NP_C / 128, (LL * BS) / 128);
        k_gemm<<<grid, 256>>>(chs, CEP, bpack + PK_C1, NP_C, cbih + CG, cbhh + CG, cxg, CG, CG, CEP / 8);
    }
    // 5: char layer 1 (x from cxg; writes seqin char slice)
    k_char_persist<<<256, 256, CHP_SMEM>>>(cWhh + CG * CE, cxg, nullptr, nullptr, nullptr, seqin);
    // 6: bilstm0 input gemm  (profiled slot)
    {
        dim3 grid(NP_B / 128, (SS * BB) / 128);
        k_gemm<<<grid, 256>>>(seqin, IN0P, bpack + PK_B0, NP_B, b0bih, b0bhh, bxg, 2 * HG, 2 * HG, IN0P / 8);
    }
    // 7: bilstm0
    k_bilstm_persist<<<BLP_NBLK, BLP_NT, BLP_SMEM>>>(b0Whh, bxg, bh, h0, 0u);
    // 8: bilstm1 input gemm
    {
        dim3 grid(NP_B / 128, (SS * BB) / 128);
        k_gemm<<<grid, 256>>>(h0, IN1, bpack + PK_B1, NP_B, b1bih, b1bhh, bxg, 2 * HG, 2 * HG, IN1 / 8);
    }
    // 9: bilstm1
    k_bilstm_persist<<<BLP_NBLK, BLP_NT, BLP_SMEM>>>(b1Whh, bxg, bh, h1, 1000u);
    // 10: FC + log-softmax
    k_fc_lsm<<<SS * BB / 8, 512>>>(h1, fcW, fcb, out);
}

// round 17
// speedup vs baseline: 1.0318x; 1.0318x over previous
#include <cuda_runtime.h>
#include <cuda_bf16.h>
#include <math.h>

typedef unsigned long long ull;

// ---------------- problem constants ----------------
#define BB   64
#define SS   256
#define LL   16
#define CE   50
#define EE   100
#define HH   300
#define IN0  150
#define IN1  600
#define NCLS 50
#define BS   (BB*SS)     // 16384
#define CG   (4*CE)      // 200
#define HG   (4*HH)      // 1200
#define CVOC 128

// padded strides
#define CEP  56
#define IN0P 152
#define NP_C 256
#define NP_B 2432
#define XST  204         // char x smem row stride (16B aligned)

// pack buffer offsets (floats)
#define PK_C0 0
#define PK_C1 (CEP*NP_C)
#define PK_B0 (2*CEP*NP_C)
#define PK_B1 (PK_B0 + IN0P*NP_B)
#define PK_TOT (PK_B1 + IN1*NP_B)

// ---------------- device scratch ----------------
__device__ float g_ctab[CVOC*CG];            // layer-0 x-gate table [128][200]
__device__ float g_cxg [(long)LL*BS*CG];     // layer-1 xg
__device__ float g_chs [(long)LL*BS*CEP];    // layer-0 h sequence (layer-1 GEMM input)
__device__ float g_seqin[SS*BB*IN0P];
__device__ float g_bxg [(long)SS*BB*2*HG];
__device__ float g_h0  [(long)SS*BB*2*HH];
__device__ float g_h1  [(long)SS*BB*2*HH];
__device__ float g_bh  [2*2*BB*HH];
__device__ float g_bpack[PK_TOT];

// barrier state
__device__ unsigned g_flags[2][1920];
__device__ volatile unsigned g_gen2[2];

// ---------------- helpers ----------------
__device__ __forceinline__ float sigf(float x) { return 1.f / (1.f + expf(-x)); }

__device__ __forceinline__ ull pk2(float x, float y) {
    ull r; asm("mov.b64 %0, {%1,%2};" : "=l"(r) : "f"(x), "f"(y)); return r;
}
__device__ __forceinline__ ull f2fma(ull a, ull b, ull c) {
    ull d; asm("fma.rn.f32x2 %0, %1, %2, %3;" : "=l"(d) : "l"(a), "l"(b), "l"(c)); return d;
}
__device__ __forceinline__ void unpk2(ull v, float& x, float& y) {
    asm("mov.b64 {%0,%1}, %2;" : "=f"(x), "=f"(y) : "l"(v));
}
__device__ __forceinline__ float sum2(ull v) { float x, y; unpk2(v, x, y); return x + y; }

// ---------------- two-level flag barrier (R12, measured-good) ----------------
__device__ __forceinline__ void gsync2(int dir, int lbk, unsigned &lg) {
    __syncthreads();
    const unsigned target = lg + 1;
    if (threadIdx.x == 0) {
        __threadfence();
        *(volatile unsigned*)&g_flags[dir][lbk * 32] = target;
    }
    if (lbk == 0) {
        if (threadIdx.x < 60) {
            volatile unsigned* f = &g_flags[dir][threadIdx.x * 32];
            int spins = 0;
            while (*f < target) { if (++spins > 512) __nanosleep(32); }
        }
        __syncthreads();
        if (threadIdx.x == 0) {
            __threadfence();
            g_gen2[dir] = target;
        }
    } else {
        if (threadIdx.x == 0) {
            int spins = 0;
            while (g_gen2[dir] < target) { if (++spins > 512) __nanosleep(32); }
            __threadfence();
        }
    }
    __syncthreads();
    lg = target;
}

// ---------------- ctable: flags reset + char layer-0 vocab table + seqin word part ----------------
__global__ void k_ctable(const float* __restrict__ char_embed, const float* __restrict__ cWih,
                         const float* __restrict__ cbih, const float* __restrict__ cbhh,
                         const int* __restrict__ word_ids, const float* __restrict__ word_embed,
                         float* __restrict__ table, float* __restrict__ seqin) {
    if (blockIdx.x == 0) {
        for (int e = threadIdx.x; e < 2 * 1920; e += 256)
            ((unsigned*)g_flags)[e] = 0;
        if (threadIdx.x < 2) g_gen2[threadIdx.x] = 0;
    }
    const long NT = (long)CVOC * CG;           // 25600
    const long NS = (long)SS * BB * IN0P;
    long i = (long)blockIdx.x * blockDim.x + threadIdx.x;
    if (i < NT) {
        int v = (int)(i / CG), g = (int)(i % CG);
        float acc = cbih[g] + cbhh[g];
        const float* ev = char_embed + (long)v * CE;
        const float* wv = cWih + (long)g * CE;
#pragma unroll 10
        for (int k = 0; k < CE; k++) acc += ev[k] * wv[k];
        table[i] = acc;
    } else if (i < NT + NS) {
        long i2 = i - NT;
        int d = (int)(i2 % IN0P);
        long r = i2 / IN0P;
        int b = (int)(r & 63);
        int s = (int)(r >> 6);
        if (d < EE)
            seqin[i2] = word_embed[(long)word_ids[(long)b * SS + s] * EE + d];
        else if (d >= IN0)
            seqin[i2] = 0.f;
        // d in [100,150): written by char layer-1 persist
    }
}

// ---------------- pack all weights ----------------
__global__ void k_packall(const float* __restrict__ cWih,
                          const float* __restrict__ b0Wih,
                          const float* __restrict__ b1Wih,
                          float* __restrict__ dst) {
    for (long i = (long)blockIdx.x * blockDim.x + threadIdx.x; i < PK_TOT;
         i += (long)gridDim.x * blockDim.x) {
        float v = 0.f;
        if (i < PK_B0) {
            int lay = (i >= PK_C1);
            long i2 = i - (lay ? PK_C1 : 0);
            int k = (int)(i2 / NP_C), n = (int)(i2 % NP_C);
            if (n < CG && k < CE) v = cWih[(long)lay * CG * CE + (long)n * CE + k];
        } else if (i < PK_B1) {
            long i2 = i - PK_B0;
            int k = (int)(i2 / NP_B), n = (int)(i2 % NP_B);
            if (n < 2 * HG && k < IN0) v = b0Wih[(long)n * IN0 + k];
        } else {
            long i2 = i - PK_B1;
            int k = (int)(i2 / NP_B), n = (int)(i2 % NP_B);
            if (n < 2 * HG && k < IN1) v = b1Wih[(long)n * IN1 + k];
        }
        dst[i] = v;
    }
}

// ---------------- GEMM v1 (measured-good): C = A[M,lda] @ Bp[KP,NP] + b1 + b2 ----------------
__global__ __launch_bounds__(256, 2) void k_gemm(
    const float* __restrict__ A, int lda,
    const float* __restrict__ Bp, int NP,
    const float* __restrict__ bias1, const float* __restrict__ bias2,
    float* __restrict__ C, int N, int ldc, int kt)
{
    __shared__ __align__(16) float As[2][8][128];
    __shared__ __align__(16) float Bs[2][8][128];
    const int tid = threadIdx.x;
    const int tx = tid & 15, ty = tid >> 4;
    const int row0 = blockIdx.y * 128, col0 = blockIdx.x * 128;

    ull acc[8][4];
#pragma unroll
    for (int i = 0; i < 8; i++)
#pragma unroll
        for (int jp = 0; jp < 4; jp++) acc[i][jp] = 0ull;

    const int ar = tid >> 1, ak = (tid & 1) * 4;
    const int bk = tid >> 5, bn = (tid & 31) * 4;
    const float* Aptr = A + (long)(row0 + ar) * lda + ak;
    const float* Bptr = Bp + (long)bk * NP + col0 + bn;

    {
        float4 av = *(const float4*)Aptr;
        As[0][ak + 0][ar] = av.x; As[0][ak + 1][ar] = av.y;
        As[0][ak + 2][ar] = av.z; As[0][ak + 3][ar] = av.w;
        *(float4*)&Bs[0][bk][bn] = *(const float4*)Bptr;
    }
    __syncthreads();

    for (int it = 0; it < kt; it++) {
        int cur = it & 1;
        if (it + 1 < kt) {
            float4 av = *(const float4*)(Aptr + (it + 1) * 8);
            float4 bv = *(const float4*)(Bptr + (long)(it + 1) * 8 * NP);
            As[cur ^ 1][ak + 0][ar] = av.x; As[cur ^ 1][ak + 1][ar] = av.y;
            As[cur ^ 1][ak + 2][ar] = av.z; As[cur ^ 1][ak + 3][ar] = av.w;
            *(float4*)&Bs[cur ^ 1][bk][bn] = bv;
        }
#pragma unroll
        for (int k = 0; k < 8; k++) {
            float4 a0 = *(const float4*)&As[cur][k][ty * 4];
            float4 a1 = *(const float4*)&As[cur][k][64 + ty * 4];
            ulonglong2 b0 = *(const ulonglong2*)&Bs[cur][k][tx * 4];
            ulonglong2 b1 = *(const ulonglong2*)&Bs[cur][k][64 + tx * 4];
            ull ap;
#define ROWF(ii, sc) \
            ap = pk2(sc, sc); \
            acc[ii][0] = f2fma(ap, b0.x, acc[ii][0]); \
            acc[ii][1] = f2fma(ap, b0.y, acc[ii][1]); \
            acc[ii][2] = f2fma(ap, b1.x, acc[ii][2]); \
            acc[ii][3] = f2fma(ap, b1.y, acc[ii][3]);
            ROWF(0, a0.x) ROWF(1, a0.y) ROWF(2, a0.z) ROWF(3, a0.w)
            ROWF(4, a1.x) ROWF(5, a1.y) ROWF(6, a1.z) ROWF(7, a1.w)
#undef ROWF
        }
        __syncthreads();
    }

#pragma unroll
    for (int i = 0; i < 8; i++) {
        int r = row0 + (i < 4 ? ty * 4 + i : 64 + ty * 4 + (i - 4));
#pragma unroll
        for (int jp = 0; jp < 4; jp++) {
            float x, y; unpk2(acc[i][jp], x, y);
            int c0 = col0 + (jp < 2 ? tx * 4 + jp * 2 : 64 + tx * 4 + (jp - 2) * 2);
            if (c0 < N)     C[(long)r * ldc + c0]     = x + bias1[c0] + bias2[c0];
            if (c0 + 1 < N) C[(long)r * ldc + c0 + 1] = y + bias1[c0 + 1] + bias2[c0 + 1];
        }
    }
}

// ---------------- char LSTM layer: h in smem; x from cxg (L1) or vocab table (L0) ----------------
#define CHP_SMEM (((200*52 + 64*XST + 64*52) * 4) + 4096)
__global__ __launch_bounds__(256, 2) void k_char_persist(
    const float* __restrict__ Whh,      // [200][50]
    const float* __restrict__ xg,       // [16][BS][200] or NULL (L0)
    const float* __restrict__ xtable,   // [128][200] or NULL (L1)
    const int*   __restrict__ char_ids, // [BS][16] (L0 only)
    float* __restrict__ hseq,           // [16][BS][56] or NULL
    float* __restrict__ seqchar)        // seqin base or NULL (L1: write char slice at t=15)
{
    extern __shared__ float sm[];
    float* Ws  = sm;                        // [200][52]
    float* xs  = sm + 200 * 52;             // [64][XST]
    float* hsm = sm + 200 * 52 + 64 * XST;  // [64][52]
    int*   ids = (int*)(sm + 200 * 52 + 64 * XST + 64 * 52);  // [64*16]
    const int tid = threadIdx.x;
    const int nl  = tid & 63;
    const int jg  = tid >> 6;        // 0..3
    const int n0  = blockIdx.x * 64;
    const int jb  = jg * 13;

    for (int e = tid; e < 200 * 52; e += 256) {
        int k = e % 52, r = e / 52;
        Ws[e] = (k < 50) ? Whh[r * 50 + k] : 0.f;
    }
    for (int e = tid; e < 64 * 52; e += 256) hsm[e] = 0.f;
    if (xtable) {
        for (int e = tid; e < 64 * LL; e += 256) ids[e] = char_ids[(long)n0 * LL + e];
    }
    float c[13];
#pragma unroll
    for (int q = 0; q < 13; q++) c[q] = 0.f;
    __syncthreads();

    for (int t = 0; t < LL; t++) {
        if (xtable) {
            for (int e = tid; e < 64 * 50; e += 256) {
                int n = e / 50, q = e % 50;
                int id = ids[n * LL + t];
                *(float4*)&xs[n * XST + q * 4] = *(const float4*)&xtable[(long)id * CG + q * 4];
            }
        } else {
            const float4* xsrc = (const float4*)(xg + ((long)t * BS + n0) * CG);
            for (int e = tid; e < 64 * 50; e += 256) {
                int n = e / 50, q = e % 50;
                *(float4*)&xs[n * XST + q * 4] = xsrc[(long)n * 50 + q];
            }
        }
        __syncthreads();

        ulonglong2 hreg[13];
        {
            const ulonglong2* hp = (const ulonglong2*)(hsm + nl * 52);
#pragma unroll
            for (int q = 0; q < 13; q++) hreg[q] = hp[q];
        }
        __syncthreads();

        const float* xrow = xs + nl * XST;
#pragma unroll
        for (int jj = 0; jj < 13; jj++) {
            int jv = jb + jj;
            bool act = (jv < 50);
            int jvc = act ? jv : 0;
            ull a0 = 0ull, a1 = 0ull, a2 = 0ull, a3 = 0ull;
            const ulonglong2* wi = (const ulonglong2*)(Ws + (      jvc) * 52);
            const ulonglong2* wf = (const ulonglong2*)(Ws + ( 50 + jvc) * 52);
            const ulonglong2* wg = (const ulonglong2*)(Ws + (100 + jvc) * 52);
            const ulonglong2* wo = (const ulonglong2*)(Ws + (150 + jvc) * 52);
#pragma unroll
            for (int q = 0; q < 13; q++) {
                ulonglong2 hv = hreg[q];
                ulonglong2 w;
                w = wi[q]; a0 = f2fma(w.x, hv.x, a0); a0 = f2fma(w.y, hv.y, a0);
                w = wf[q]; a1 = f2fma(w.x, hv.x, a1); a1 = f2fma(w.y, hv.y, a1);
                w = wg[q]; a2 = f2fma(w.x, hv.x, a2); a2 = f2fma(w.y, hv.y, a2);
                w = wo[q]; a3 = f2fma(w.x, hv.x, a3); a3 = f2fma(w.y, hv.y, a3);
            }
            if (act) {
                float g0 = sum2(a0) + xrow[jv];
                float g1 = sum2(a1) + xrow[50 + jv];
                float g2 = sum2(a2) + xrow[100 + jv];
                float g3 = sum2(a3) + xrow[150 + jv];
                float cn = sigf(g1) * c[jj] + sigf(g0) * tanhf(g2);
                float h  = sigf(g3) * tanhf(cn);
                c[jj] = cn;
                hsm[nl * 52 + jv] = h;
            }
        }
        __syncthreads();
        if (hseq) {
            float* sd = hseq + ((long)t * BS + n0) * CEP;
            for (int e = tid; e < 64 * CEP; e += 256) {
                int n = e / CEP, k = e % CEP;
                sd[e] = (k < 50) ? hsm[n * 52 + k] : 0.f;
            }
        }
        if (seqchar && t == LL - 1) {
            int b  = n0 / SS;
            int s0 = n0 % SS;
            for (int e = tid; e < 64 * 50; e += 256) {
                int nlw = e / 50, k = e % 50;
                seqchar[((long)(s0 + nlw) * BB + b) * IN0P + EE + k] = hsm[nlw * 52 + k];
            }
        }
    }
}

// ---------------- persistent bilstm layer (R12-exact: 160 thr, 2 batches/thread) ----------------
#define BLP_NBLK 120
#define BLP_NT   160
#define BLP_SMEM ((6000 + 64*308) * 4)
__global__ __launch_bounds__(BLP_NT, 1) void k_bilstm_persist(
    const float* __restrict__ Whh,   // [2][1200][300]
    const float* __restrict__ xg,    // [256][64][2400]
    float* __restrict__ hbuf,        // [2 ping][2 dir][64][300]
    float* __restrict__ seq,         // [256][64][600]
    unsigned gbase)
{
    extern __shared__ float sm[];
    float* Ws = sm;           // [4 gate][5 unit][300]
    float* hs = sm + 6000;    // [64][308]
    const int bk  = blockIdx.x;
    const int dir = bk / 60;
    const int lbk = bk % 60;
    const int jbase = lbk * 5;
    const int tid = threadIdx.x;
    const int ul = tid % 5;
    const int b2 = tid / 5;          // 0..31
    const int ba = 2 * b2, bbn = 2 * b2 + 1;
    const int j  = jbase + ul;
    unsigned lg = gbase;

    const float* wb = Whh + (long)dir * HG * HH;
    for (int e = tid; e < 6000; e += BLP_NT) {
        int k = e % 300; int r = e / 300; int u = r % 5; int g = r / 5;
        Ws[e] = wb[(long)(g * 300 + jbase + u) * 300 + k];
    }
    for (int e = lbk * BLP_NT + tid; e < BB * HH; e += 60 * BLP_NT)
        hbuf[(long)dir * BB * HH + e] = 0.f;
    float ca = 0.f, cb = 0.f;

    float xr[8];
    {
        int te = dir ? (SS - 1) : 0;
        const float* xa = xg + ((long)te * BB + ba)  * (2 * HG) + dir * HG;
        const float* xv = xg + ((long)te * BB + bbn) * (2 * HG) + dir * HG;
        xr[0] = xa[j]; xr[1] = xa[300 + j]; xr[2] = xa[600 + j]; xr[3] = xa[900 + j];
        xr[4] = xv[j]; xr[5] = xv[300 + j]; xr[6] = xv[600 + j]; xr[7] = xv[900 + j];
    }
    gsync2(dir, lbk, lg);

    const ulonglong2* w0 = (const ulonglong2*)(Ws + (0 * 5 + ul) * 300);
    const ulonglong2* w1 = (const ulonglong2*)(Ws + (1 * 5 + ul) * 300);
    const ulonglong2* w2 = (const ulonglong2*)(Ws + (2 * 5 + ul) * 300);
    const ulonglong2* w3 = (const ulonglong2*)(Ws + (3 * 5 + ul) * 300);
    float4* hs4 = (float4*)hs;

    for (int t = 0; t < SS; t++) {
        int pp = t & 1;
        int te = dir ? (SS - 1 - t) : t;

        const float4* src = (const float4*)(hbuf + ((long)pp * 2 + dir) * BB * HH);
        for (int e = tid; e < 4800; e += BLP_NT) {
            int bb = e / 75, k4 = e % 75;
            hs4[bb * 77 + k4] = src[e];
        }
        __syncthreads();

        ull a0 = 0ull, a1 = 0ull, a2 = 0ull, a3 = 0ull;
        ull d0 = 0ull, d1 = 0ull, d2 = 0ull, d3 = 0ull;
        const ulonglong2* ra = (const ulonglong2*)(hs + ba  * 308);
        const ulonglong2* rb = (const ulonglong2*)(hs + bbn * 308);
#pragma unroll
        for (int q = 0; q < 75; q++) {
            ulonglong2 ha = ra[q];
            ulonglong2 hb = rb[q];
            ulonglong2 w;
            w = w0[q]; a0 = f2fma(w.x, ha.x, a0); a0 = f2fma(w.y, ha.y, a0);
                       d0 = f2fma(w.x, hb.x, d0); d0 = f2fma(w.y, hb.y, d0);
            w = w1[q]; a1 = f2fma(w.x, ha.x, a1); a1 = f2fma(w.y, ha.y, a1);
                       d1 = f2fma(w.x, hb.x, d1); d1 = f2fma(w.y, hb.y, d1);
            w = w2[q]; a2 = f2fma(w.x, ha.x, a2); a2 = f2fma(w.y, ha.y, a2);
                       d2 = f2fma(w.x, hb.x, d2); d2 = f2fma(w.y, hb.y, d2);
            w = w3[q]; a3 = f2fma(w.x, ha.x, a3); a3 = f2fma(w.y, ha.y, a3);
                       d3 = f2fma(w.x, hb.x, d3); d3 = f2fma(w.y, hb.y, d3);
        }
        {
            float g0 = sum2(a0) + xr[0];
            float g1 = sum2(a1) + xr[1];
            float g2 = sum2(a2) + xr[2];
            float g3 = sum2(a3) + xr[3];
            float cn = sigf(g1) * ca + sigf(g0) * tanhf(g2);
            float h  = sigf(g3) * tanhf(cn);
            ca = cn;
            hbuf[((long)(pp ^ 1) * 2 + dir) * BB * HH + ba * HH + j] = h;
            seq[((long)te * BB + ba) * (2 * HH) + dir * HH + j] = h;
        }
        {
            float g0 = sum2(d0) + xr[4];
            float g1 = sum2(d1) + xr[5];
            float g2 = sum2(d2) + xr[6];
            float g3 = sum2(d3) + xr[7];
            float cn = sigf(g1) * cb + sigf(g0) * tanhf(g2);
            float h  = sigf(g3) * tanhf(cn);
            cb = cn;
            hbuf[((long)(pp ^ 1) * 2 + dir) * BB * HH + bbn * HH + j] = h;
            seq[((long)te * BB + bbn) * (2 * HH) + dir * HH + j] = h;
        }
        if (t + 1 < SS) {
            int te2 = dir ? (SS - 2 - t) : (t + 1);
            const float* xa = xg + ((long)te2 * BB + ba)  * (2 * HG) + dir * HG;
            const float* xv = xg + ((long)te2 * BB + bbn) * (2 * HG) + dir * HG;
            xr[0] = xa[j]; xr[1] = xa[300 + j]; xr[2] = xa[600 + j]; xr[3] = xa[900 + j];
            xr[4] = xv[j]; xr[5] = xv[300 + j]; xr[6] = xv[600 + j]; xr[7] = xv[900 + j];
        }
        gsync2(dir, lbk, lg);
    }
}

// ---------------- FC + log-softmax: 8 rows per block, 512 threads ----------------
__global__ __launch_bounds__(512) void k_fc_lsm(
    const float* __restrict__ h1, const float* __restrict__ fcW,
    const float* __restrict__ fcb, float* __restrict__ out) {
    __shared__ float hrow[8 * IN1];
    __shared__ float logits[8 * NCLS];
    __shared__ float lse[8];
    const int tid = threadIdx.x;
    const int r0 = blockIdx.x * 8;
    for (int e = tid; e < 8 * IN1; e += 512) hrow[e] = h1[(long)r0 * IN1 + e];
    __syncthreads();
    const int rl = tid / NCLS, cc = tid % NCLS;
    if (tid < 8 * NCLS) {
        float acc = 0.f;
        const float4* w  = (const float4*)(fcW + cc * IN1);
        const float4* hv = (const float4*)(hrow + rl * IN1);
#pragma unroll 10
        for (int k = 0; k < IN1 / 4; k++) {
            float4 a = __ldg(w + k), x = hv[k];
            acc += a.x * x.x + a.y * x.y + a.z * x.z + a.w * x.w;
        }
        logits[rl * NCLS + cc] = acc + fcb[cc];
    }
    __syncthreads();
    if (tid < 8) {
        float m = -1e30f;
        for (int c = 0; c < NCLS; c++) m = fmaxf(m, logits[tid * NCLS + c]);
        float sum = 0.f;
        for (int c = 0; c < NCLS; c++) sum += expf(logits[tid * NCLS + c] - m);
        lse[tid] = m + logf(sum);
    }
    __syncthreads();
    if (tid < 8 * NCLS) {
        int r = r0 + rl;
        int s = r >> 6, b = r & 63;
        out[((long)(b * SS + s)) * NCLS + cc] = logits[rl * NCLS + cc] - lse[rl];
    }
}

// ---------------- host orchestration ----------------
extern "C" void kernel_launch(void* const* d_in, const int* in_sizes, int n_in,
                              void* d_out, int out_size) {
    const int*   word_ids   = (const int*)  d_in[0];
    const int*   char_ids   = (const int*)  d_in[1];
    const float* word_embed = (const float*)d_in[2];
    const float* char_embed = (const float*)d_in[3];
    const float* cWih  = (const float*)d_in[4];
    const float* cWhh  = (const float*)d_in[5];
    const float* cbih  = (const float*)d_in[6];
    const float* cbhh  = (const float*)d_in[7];
    const float* b0Wih = (const float*)d_in[8];
    const float* b0Whh = (const float*)d_in[9];
    const float* b0bih = (const float*)d_in[10];
    const float* b0bhh = (const float*)d_in[11];
    const float* b1Wih = (const float*)d_in[12];
    const float* b1Whh = (const float*)d_in[13];
    const float* b1bih = (const float*)d_in[14];
    const float* b1bhh = (const float*)d_in[15];
    const float* fcW   = (const float*)d_in[16];
    const float* fcb   = (const float*)d_in[17];
    float* out = (float*)d_out;

    float *ctab, *cxg, *chs, *seqin, *bxg, *h0, *h1, *bh, *bpack;
    cudaGetSymbolAddress((void**)&ctab,  g_ctab);
    cudaGetSymbolAddress((void**)&cxg,   g_cxg);
    cudaGetSymbolAddress((void**)&chs,   g_chs);
    cudaGetSymbolAddress((void**)&seqin, g_seqin);
    cudaGetSymbolAddress((void**)&bxg,   g_bxg);
    cudaGetSymbolAddress((void**)&h0,    g_h0);
    cudaGetSymbolAddress((void**)&h1,    g_h1);
    cudaGetSymbolAddress((void**)&bh,    g_bh);
    cudaGetSymbolAddress((void**)&bpack, g_bpack);

    cudaFuncSetAttribute(k_char_persist,   cudaFuncAttributeMaxDynamicSharedMemorySize, CHP_SMEM);
    cudaFuncSetAttribute(k_bilstm_persist, cudaFuncAttributeMaxDynamicSharedMemorySize, BLP_SMEM);

    // 1: ctable (flags reset + vocab table + seqin word part)
    {
        long n = (long)CVOC * CG + (long)SS * BB * IN0P;
        k_ctable<<<(int)((n + 255) / 256), 256>>>(char_embed, cWih, cbih, cbhh,
                                                  word_ids, word_embed, ctab, seqin);
    }
    // 2: pack all weights
    k_packall<<<2048, 256>>>(cWih, b0Wih, b1Wih, bpack);
    // 3: char layer 0 (x from vocab table; writes chs)
    k_char_persist<<<256, 256, CHP_SMEM>>>(cWhh, nullptr, ctab, char_ids, chs, nullptr);
    // 4: char layer-1 input gemm
    {
        dim3 grid(NP_C / 128, (LL * BS) / 128);
        k_gemm<<<grid, 256>>>(chs, CEP, bpack + PK_C1, NP_C, cbih + CG, cbhh + CG, cxg, CG, CG, CEP / 8);
    }
    // 5: char layer 1 (x from cxg; writes seqin char slice)
    k_char_persist<<<256, 256, CHP_SMEM>>>(cWhh + CG * CE, cxg, nullptr, nullptr, nullptr, seqin);
    // 6: bilstm0 input gemm  (profiled slot)
    {
        dim3 grid(NP_B / 128, (SS * BB) / 128);
        k_gemm<<<grid, 256>>>(seqin, IN0P, bpack + PK_B0, NP_B, b0bih, b0bhh, bxg, 2 * HG, 2 * HG, IN0P / 8);
    }
    // 7: bilstm0
    k_bilstm_persist<<<BLP_NBLK, BLP_NT, BLP_SMEM>>>(b0Whh, bxg, bh, h0, 0u);
    // 8: bilstm1 input gemm
    {
        dim3 grid(NP_B / 128, (SS * BB) / 128);
        k_gemm<<<grid, 256>>>(h0, IN1, bpack + PK_B1, NP_B, b1bih, b1bhh, bxg, 2 * HG, 2 * HG, IN1 / 8);
    }
    // 9: bilstm1
    k_bilstm_persist<<<BLP_NBLK, BLP_NT, BLP_SMEM>>>(b1Whh, bxg, bh, h1, 1000u);
    // 10: FC + log-softmax
    k_fc_lsm<<<SS * BB / 8, 512>>>(h1, fcW, fcb, out);
}